// round 2
// baseline (speedup 1.0000x reference)
#include <cuda_runtime.h>
#include <cuda_fp16.h>
#include <cstdint>
#include <math.h>

// Problem constants: B=128, S=512, I=128, Hd=512
#define BATCH   128
#define SEQ     512
#define IDIM    128
#define HDIM    512
#define G3      1536            // 3*Hd
#define MTOT    65536           // B*S
#define H_TAIL  33488896ull     // B*(S-1)*Hd

// Scratch (allocation-free rule: __device__ globals)
__device__ __half g_Wh[G3 * IDIM];   // fp16 fused weight  W = w_ih @ w_emb  [1536][128]
__device__ float  g_bias[G3];        // fused bias: w_ih@b_emb + b_ih (+ b_hh for r,z gates)

// ---------------------------------------------------------------------------
// Precompute 1: W[g][i] = sum_h w_ih[g][h] * w_emb[h][i]  (fp32, then fp16)
// grid = 192 blocks (8 g-rows each), 128 threads (one i each)
// ---------------------------------------------------------------------------
__global__ void precomp_W(const float* __restrict__ w_ih,
                          const float* __restrict__ w_emb) {
    __shared__ float wihs[8][512];
    const int g0  = blockIdx.x * 8;
    const int tid = threadIdx.x;

    // stage 8 rows of w_ih (8*512 floats = 1024 float4)
    const float4* src = (const float4*)(w_ih + (size_t)g0 * 512);
    float4* dst = (float4*)&wihs[0][0];
#pragma unroll
    for (int it = 0; it < 8; it++) dst[tid + it * 128] = src[tid + it * 128];
    __syncthreads();

    const int i = tid;
    float acc[8] = {0.f,0.f,0.f,0.f,0.f,0.f,0.f,0.f};
#pragma unroll 4
    for (int h = 0; h < 512; h++) {
        const float we = w_emb[h * IDIM + i];
#pragma unroll
        for (int g = 0; g < 8; g++) acc[g] = fmaf(wihs[g][h], we, acc[g]);
    }
#pragma unroll
    for (int g = 0; g < 8; g++)
        g_Wh[(size_t)(g0 + g) * IDIM + i] = __float2half_rn(acc[g]);
}

// ---------------------------------------------------------------------------
// Precompute 2: bias[g] = w_ih[g]·b_emb + b_ih[g] + (g<1024 ? b_hh[g] : 0)
// one warp per g; grid = 192 blocks x 256 threads (8 warps)
// ---------------------------------------------------------------------------
__global__ void precomp_bias(const float* __restrict__ w_ih,
                             const float* __restrict__ b_emb,
                             const float* __restrict__ b_ih,
                             const float* __restrict__ b_hh) {
    const int warp = threadIdx.x >> 5, lane = threadIdx.x & 31;
    const int g = blockIdx.x * 8 + warp;
    const float* wg = w_ih + (size_t)g * 512;
    float acc = 0.f;
#pragma unroll
    for (int h = lane; h < 512; h += 32) acc = fmaf(wg[h], b_emb[h], acc);
#pragma unroll
    for (int off = 16; off; off >>= 1) acc += __shfl_xor_sync(0xffffffffu, acc, off);
    if (lane == 0) {
        float v = acc + b_ih[g];
        if (g < 1024) v += b_hh[g];   // fold b_hr / b_hz into the linear bias
        g_bias[g] = v;
    }
}

// ---------------------------------------------------------------------------
// mma.sync helpers
// ---------------------------------------------------------------------------
__device__ __forceinline__ void ldsm4(uint32_t* r, uint32_t addr) {
    asm volatile("ldmatrix.sync.aligned.m8n8.x4.shared.b16 {%0,%1,%2,%3}, [%4];\n"
                 : "=r"(r[0]), "=r"(r[1]), "=r"(r[2]), "=r"(r[3]) : "r"(addr));
}
__device__ __forceinline__ void ldsm2(uint32_t* r, uint32_t addr) {
    asm volatile("ldmatrix.sync.aligned.m8n8.x2.shared.b16 {%0,%1}, [%2];\n"
                 : "=r"(r[0]), "=r"(r[1]) : "r"(addr));
}
__device__ __forceinline__ void mma16816(float* c, const uint32_t* a, const uint32_t* b) {
    asm volatile("mma.sync.aligned.m16n8k16.row.col.f32.f16.f16.f32 "
                 "{%0,%1,%2,%3}, {%4,%5,%6,%7}, {%8,%9}, {%0,%1,%2,%3};\n"
                 : "+f"(c[0]), "+f"(c[1]), "+f"(c[2]), "+f"(c[3])
                 : "r"(a[0]), "r"(a[1]), "r"(a[2]), "r"(a[3]), "r"(b[0]), "r"(b[1]));
}

// ---------------------------------------------------------------------------
// Fused main kernel:
//   gi = (x_hi + x_lo) @ W_fp16^T + bias       (three 128x64 gate GEMMs / CTA)
//   h  = (1 - sigmoid(gz)) * tanh(gn + sigmoid(gr) * b_hn)
//   scatter-store to H (s<511) and h_last (s==511)
// grid = (512 m-blocks, 8 hd-blocks), 256 threads (8 warps: 4 along M, 2 along N)
// ---------------------------------------------------------------------------
#define AROW 136                // padded row stride in halves (272B, conflict-free ldmatrix)
#define SMEM_BYTES 122880

__global__ __launch_bounds__(256, 1)
void fused_main(const float* __restrict__ x,
                const float* __restrict__ b_hh,
                float* __restrict__ out) {
    extern __shared__ __align__(16) char smem_raw[];
    __half* Ahi = (__half*)smem_raw;                 // 128 x 136
    __half* Alo = Ahi + 128 * AROW;                  // 128 x 136
    __half* Bs  = Alo + 128 * AROW;                  // 3 gates x 64 x 136
    float*  biasS = (float*)(Bs + 3 * 64 * AROW);    // [4][64]: r,z,n bias + b_hn

    const int tid = threadIdx.x;
    const int m0  = blockIdx.x * 128;
    const int hd0 = blockIdx.y * 64;

    // ---- load & split x tile (128 rows x 128 fp32) into hi/lo fp16 ----
    {
        const float4* xsrc = (const float4*)(x + (size_t)m0 * IDIM);
#pragma unroll
        for (int it = 0; it < 16; it++) {
            const int idx = tid + it * 256;          // 0..4095 float4s
            const int row = idx >> 5;
            const int c4  = (idx & 31) << 2;
            const float4 v = xsrc[idx];
            float f[4] = {v.x, v.y, v.z, v.w};
            __half hh[4], hl[4];
#pragma unroll
            for (int j = 0; j < 4; j++) {
                hh[j] = __float2half_rn(f[j]);
                hl[j] = __float2half_rn(f[j] - __half2float(hh[j]));
            }
            __half2* ph = (__half2*)(Ahi + row * AROW + c4);
            ph[0] = __halves2half2(hh[0], hh[1]);
            ph[1] = __halves2half2(hh[2], hh[3]);
            __half2* pl = (__half2*)(Alo + row * AROW + c4);
            pl[0] = __halves2half2(hl[0], hl[1]);
            pl[1] = __halves2half2(hl[2], hl[3]);
        }
    }

    // ---- load 3 gate B tiles (64 rows x 128 halves each) ----
    {
        const int4* wsrc = (const int4*)g_Wh;        // 16 int4 per 128-half row
#pragma unroll
        for (int it = 0; it < 12; it++) {
            const int idx  = tid + it * 256;         // 0..3071
            const int gate = idx >> 10;
            const int rem  = idx & 1023;
            const int r    = rem >> 4;
            const int c    = rem & 15;
            const int grow = gate * HDIM + hd0 + r;
            const int4 v = wsrc[grow * 16 + c];
            *(int4*)(Bs + gate * (64 * AROW) + r * AROW + c * 8) = v;
        }
    }

    // ---- bias slices for this hd block ----
    if (tid < 64) {
        const int hd = hd0 + tid;
        biasS[tid]       = g_bias[hd];               // r
        biasS[64 + tid]  = g_bias[HDIM + hd];        // z
        biasS[128 + tid] = g_bias[2 * HDIM + hd];    // n (linear part)
        biasS[192 + tid] = b_hh[2 * HDIM + hd];      // b_hn (multiplied by r)
    }
    __syncthreads();

    // ---- warp tiling: 4 warps along M (32 rows), 2 along N (32 cols) ----
    const int lane = tid & 31;
    const int warp = tid >> 5;
    const int wm = warp & 3;
    const int wn = warp >> 2;

    float acc[3][2][4][4];
#pragma unroll
    for (int g = 0; g < 3; g++)
#pragma unroll
        for (int mi = 0; mi < 2; mi++)
#pragma unroll
            for (int ni = 0; ni < 4; ni++)
#pragma unroll
                for (int j = 0; j < 4; j++) acc[g][mi][ni][j] = 0.f;

    // ldmatrix base addresses
    uint32_t a_hi_addr[2], a_lo_addr[2], b_addr[3][4];
#pragma unroll
    for (int mi = 0; mi < 2; mi++) {
        const int row = wm * 32 + mi * 16 + (lane & 15);
        const int col = (lane >> 4) << 3;
        a_hi_addr[mi] = (uint32_t)__cvta_generic_to_shared(Ahi + row * AROW + col);
        a_lo_addr[mi] = (uint32_t)__cvta_generic_to_shared(Alo + row * AROW + col);
    }
#pragma unroll
    for (int g = 0; g < 3; g++)
#pragma unroll
        for (int ni = 0; ni < 4; ni++) {
            const int row = wn * 32 + ni * 8 + (lane & 7);
            const int col = ((lane >> 3) & 1) << 3;
            b_addr[g][ni] = (uint32_t)__cvta_generic_to_shared(
                Bs + g * (64 * AROW) + row * AROW + col);
        }

    // ---- mainloop over K = 8 x 16 ----
#pragma unroll
    for (int kk = 0; kk < 8; kk++) {
        const uint32_t koff = kk * 32;               // 16 halves = 32 bytes
        uint32_t ah[2][4], al[2][4];
#pragma unroll
        for (int mi = 0; mi < 2; mi++) {
            ldsm4(ah[mi], a_hi_addr[mi] + koff);
            ldsm4(al[mi], a_lo_addr[mi] + koff);
        }
#pragma unroll
        for (int g = 0; g < 3; g++) {
#pragma unroll
            for (int ni = 0; ni < 4; ni++) {
                uint32_t br[2];
                ldsm2(br, b_addr[g][ni] + koff);
#pragma unroll
                for (int mi = 0; mi < 2; mi++) {
                    mma16816(acc[g][mi][ni], ah[mi], br);   // x_hi * W
                    mma16816(acc[g][mi][ni], al[mi], br);   // x_lo * W
                }
            }
        }
    }

    // ---- epilogue: gates + scatter store ----
#pragma unroll
    for (int mi = 0; mi < 2; mi++) {
#pragma unroll
        for (int ni = 0; ni < 4; ni++) {
            const int colL = wn * 32 + ni * 8 + (lane & 3) * 2;   // local hd
            const float br0 = biasS[colL],       br1 = biasS[colL + 1];
            const float bz0 = biasS[64 + colL],  bz1 = biasS[64 + colL + 1];
            const float bn0 = biasS[128 + colL], bn1 = biasS[128 + colL + 1];
            const float bh0 = biasS[192 + colL], bh1 = biasS[192 + colL + 1];
#pragma unroll
            for (int hseg = 0; hseg < 2; hseg++) {
                const int m = m0 + wm * 32 + mi * 16 + (lane >> 2) + hseg * 8;
                const float cr0 = acc[0][mi][ni][hseg * 2 + 0] + br0;
                const float cr1 = acc[0][mi][ni][hseg * 2 + 1] + br1;
                const float cz0 = acc[1][mi][ni][hseg * 2 + 0] + bz0;
                const float cz1 = acc[1][mi][ni][hseg * 2 + 1] + bz1;
                const float cn0 = acc[2][mi][ni][hseg * 2 + 0] + bn0;
                const float cn1 = acc[2][mi][ni][hseg * 2 + 1] + bn1;

                const float r0 = 1.f / (1.f + expf(-cr0));
                const float r1 = 1.f / (1.f + expf(-cr1));
                const float z0 = 1.f / (1.f + expf(-cz0));
                const float z1 = 1.f / (1.f + expf(-cz1));
                const float n0 = tanhf(cn0 + r0 * bh0);
                const float n1 = tanhf(cn1 + r1 * bh1);
                const float h0 = (1.f - z0) * n0;
                const float h1 = (1.f - z1) * n1;

                const int b = m >> 9;                // m / S
                const int s = m & 511;
                size_t o;
                if (s < SEQ - 1)
                    o = (size_t)(m - b) * HDIM + (hd0 + colL);          // H[b,s,:]
                else
                    o = H_TAIL + (size_t)b * HDIM + (hd0 + colL);       // h_last[0,b,:]
                *(float2*)(out + o) = make_float2(h0, h1);
            }
        }
    }
}

// ---------------------------------------------------------------------------
extern "C" void kernel_launch(void* const* d_in, const int* in_sizes, int n_in,
                              void* d_out, int out_size) {
    const float* x     = (const float*)d_in[0];
    const float* w_emb = (const float*)d_in[1];
    const float* b_emb = (const float*)d_in[2];
    const float* w_ih  = (const float*)d_in[3];
    const float* b_ih  = (const float*)d_in[4];
    const float* b_hh  = (const float*)d_in[5];
    float* out = (float*)d_out;
    (void)in_sizes; (void)n_in; (void)out_size;

    cudaFuncSetAttribute(fused_main, cudaFuncAttributeMaxDynamicSharedMemorySize,
                         SMEM_BYTES);

    precomp_W<<<192, 128>>>(w_ih, w_emb);
    precomp_bias<<<192, 256>>>(w_ih, b_emb, b_ih, b_hh);

    dim3 grid(MTOT / 128, HDIM / 64);   // (512, 8)
    fused_main<<<grid, 256, SMEM_BYTES>>>(x, b_hh, out);
}

// round 3
// speedup vs baseline: 2.0446x; 2.0446x over previous
#include <cuda_runtime.h>
#include <cuda_fp16.h>
#include <cstdint>
#include <math.h>

// Problem constants: B=128, S=512, I=128, Hd=512
#define BATCH   128
#define SEQ     512
#define IDIM    128
#define HDIM    512
#define G3      1536            // 3*Hd
#define MTOT    65536           // B*S
#define H_TAIL  33488896ull     // B*(S-1)*Hd

// Scratch (allocation-free rule: __device__ globals)
__device__ __half g_Wh[G3 * IDIM];          // fp16 fused weight W = w_ih @ w_emb
__device__ float  g_Wpart[4 * G3 * IDIM];   // K-split partials (fp32)
__device__ float  g_bias[G3];               // fused bias

// ---------------------------------------------------------------------------
// Precompute 1a: K-split partial GEMM  (4 chunks of 128 h each)
// grid = (192, 4), 128 threads. Block: 8 g-rows x 128 i x 128 h-chunk.
// ---------------------------------------------------------------------------
__global__ void precomp_W_part(const float* __restrict__ w_ih,
                               const float* __restrict__ w_emb) {
    __shared__ float wihs[8][128];
    const int g0    = blockIdx.x * 8;
    const int chunk = blockIdx.y;
    const int h0    = chunk * 128;
    const int tid   = threadIdx.x;

    // stage 8 rows x 128 h of w_ih (256 float4)
    {
        const float4* src = (const float4*)(w_ih + (size_t)g0 * 512 + h0);
        float4* dst = (float4*)&wihs[0][0];
        // rows are strided in gmem: row g occupies float4s [g*128 .. g*128+32)
#pragma unroll
        for (int it = 0; it < 2; it++) {
            const int idx = tid + it * 128;       // 0..255
            const int g   = idx >> 5;
            const int c   = idx & 31;
            dst[g * 32 + c] = src[g * 128 + c];
        }
    }
    __syncthreads();

    const int i = tid;
    float acc[8] = {0.f,0.f,0.f,0.f,0.f,0.f,0.f,0.f};
#pragma unroll 4
    for (int h = 0; h < 128; h++) {
        const float we = w_emb[(h0 + h) * IDIM + i];
#pragma unroll
        for (int g = 0; g < 8; g++) acc[g] = fmaf(wihs[g][h], we, acc[g]);
    }
#pragma unroll
    for (int g = 0; g < 8; g++)
        g_Wpart[(size_t)chunk * (G3 * IDIM) + (size_t)(g0 + g) * IDIM + i] = acc[g];
}

// ---------------------------------------------------------------------------
// Precompute 1b: reduce 4 partials -> fp16 weight (fixed order: deterministic)
// grid = 192 x 256, each thread reduces 4 elements (float4 loads)
// ---------------------------------------------------------------------------
__global__ void precomp_W_reduce() {
    const int v = blockIdx.x * 256 + threadIdx.x;       // 0..49151 float4 groups
    const float4 a = ((const float4*)g_Wpart)[v];
    const float4 b = ((const float4*)g_Wpart)[v + 49152];
    const float4 c = ((const float4*)g_Wpart)[v + 2 * 49152];
    const float4 d = ((const float4*)g_Wpart)[v + 3 * 49152];
    __half2 h01 = __halves2half2(__float2half_rn(a.x + b.x + c.x + d.x),
                                 __float2half_rn(a.y + b.y + c.y + d.y));
    __half2 h23 = __halves2half2(__float2half_rn(a.z + b.z + c.z + d.z),
                                 __float2half_rn(a.w + b.w + c.w + d.w));
    ((__half2*)g_Wh)[v * 2]     = h01;
    ((__half2*)g_Wh)[v * 2 + 1] = h23;
}

// ---------------------------------------------------------------------------
// Precompute 2: bias[g] = w_ih[g]·b_emb + b_ih[g] + (g<1024 ? b_hh[g] : 0)
// ---------------------------------------------------------------------------
__global__ void precomp_bias(const float* __restrict__ w_ih,
                             const float* __restrict__ b_emb,
                             const float* __restrict__ b_ih,
                             const float* __restrict__ b_hh) {
    const int warp = threadIdx.x >> 5, lane = threadIdx.x & 31;
    const int g = blockIdx.x * 8 + warp;
    const float* wg = w_ih + (size_t)g * 512;
    float acc = 0.f;
#pragma unroll
    for (int h = lane; h < 512; h += 32) acc = fmaf(wg[h], b_emb[h], acc);
#pragma unroll
    for (int off = 16; off; off >>= 1) acc += __shfl_xor_sync(0xffffffffu, acc, off);
    if (lane == 0) {
        float v = acc + b_ih[g];
        if (g < 1024) v += b_hh[g];
        g_bias[g] = v;
    }
}

// ---------------------------------------------------------------------------
// asm helpers
// ---------------------------------------------------------------------------
__device__ __forceinline__ void ldsm4(uint32_t* r, uint32_t addr) {
    asm volatile("ldmatrix.sync.aligned.m8n8.x4.shared.b16 {%0,%1,%2,%3}, [%4];\n"
                 : "=r"(r[0]), "=r"(r[1]), "=r"(r[2]), "=r"(r[3]) : "r"(addr));
}
__device__ __forceinline__ void ldsm2(uint32_t* r, uint32_t addr) {
    asm volatile("ldmatrix.sync.aligned.m8n8.x2.shared.b16 {%0,%1}, [%2];\n"
                 : "=r"(r[0]), "=r"(r[1]) : "r"(addr));
}
__device__ __forceinline__ void mma16816(float* c, const uint32_t* a, const uint32_t* b) {
    asm volatile("mma.sync.aligned.m16n8k16.row.col.f32.f16.f16.f32 "
                 "{%0,%1,%2,%3}, {%4,%5,%6,%7}, {%8,%9}, {%0,%1,%2,%3};\n"
                 : "+f"(c[0]), "+f"(c[1]), "+f"(c[2]), "+f"(c[3])
                 : "r"(a[0]), "r"(a[1]), "r"(a[2]), "r"(a[3]), "r"(b[0]), "r"(b[1]));
}
__device__ __forceinline__ float fast_ex2(float x) {
    float y; asm("ex2.approx.f32 %0, %1;" : "=f"(y) : "f"(x)); return y;
}
__device__ __forceinline__ float fast_rcp(float x) {
    float y; asm("rcp.approx.f32 %0, %1;" : "=f"(y) : "f"(x)); return y;
}
__device__ __forceinline__ float fsigmoid(float x) {         // 1/(1+e^-x)
    return fast_rcp(1.f + fast_ex2(-1.44269504f * x));
}
__device__ __forceinline__ float ftanh(float x) {            // 1 - 2/(1+e^{2x})
    return 1.f - 2.f * fast_rcp(1.f + fast_ex2(2.88539008f * x));
}

// ---------------------------------------------------------------------------
// Fused main kernel (single fp16 pass):
//   gi = x_fp16 @ W_fp16^T + bias   (three 128x64 gate GEMMs per CTA)
//   h  = (1 - sig(gz)) * tanh(gn + sig(gr) * b_hn)
// grid = (8 hd-blocks, 512 m-blocks)  <- hd fastest so L2 shares the x tile
// 256 threads (8 warps: 4 along M, 2 along N), 2 CTAs/SM.
// ---------------------------------------------------------------------------
#define AROW 136                 // padded row stride in halves
#define SMEM_BYTES 88064

__global__ __launch_bounds__(256, 2)
void fused_main(const float* __restrict__ x,
                const float* __restrict__ b_hh,
                float* __restrict__ out) {
    extern __shared__ __align__(16) char smem_raw[];
    __half* As = (__half*)smem_raw;                  // 128 x 136
    __half* Bs = As + 128 * AROW;                    // 3 gates x 64 x 136
    float*  biasS = (float*)(Bs + 3 * 64 * AROW);    // [4][64]

    const int tid = threadIdx.x;
    const int hd0 = blockIdx.x * 64;
    const int m0  = blockIdx.y * 128;

    // ---- load x tile (128 x 128 fp32) -> fp16 smem ----
    {
        const float4* xsrc = (const float4*)(x + (size_t)m0 * IDIM);
#pragma unroll
        for (int it = 0; it < 16; it++) {
            const int idx = tid + it * 256;          // 0..4095 float4s
            const int row = idx >> 5;
            const int c4  = (idx & 31) << 2;
            const float4 v = xsrc[idx];
            __half2* ph = (__half2*)(As + row * AROW + c4);
            ph[0] = __halves2half2(__float2half_rn(v.x), __float2half_rn(v.y));
            ph[1] = __halves2half2(__float2half_rn(v.z), __float2half_rn(v.w));
        }
    }

    // ---- load 3 gate B tiles (64 rows x 128 halves each) ----
    {
        const int4* wsrc = (const int4*)g_Wh;
#pragma unroll
        for (int it = 0; it < 12; it++) {
            const int idx  = tid + it * 256;         // 0..3071
            const int gate = idx >> 10;
            const int rem  = idx & 1023;
            const int r    = rem >> 4;
            const int c    = rem & 15;
            const int grow = gate * HDIM + hd0 + r;
            *(int4*)(Bs + gate * (64 * AROW) + r * AROW + c * 8) = wsrc[grow * 16 + c];
        }
    }

    if (tid < 64) {
        const int hd = hd0 + tid;
        biasS[tid]       = g_bias[hd];               // r
        biasS[64 + tid]  = g_bias[HDIM + hd];        // z
        biasS[128 + tid] = g_bias[2 * HDIM + hd];    // n (linear)
        biasS[192 + tid] = b_hh[2 * HDIM + hd];      // b_hn
    }
    __syncthreads();

    const int lane = tid & 31;
    const int warp = tid >> 5;
    const int wm = warp & 3;        // 4 warps along M (32 rows each)
    const int wn = warp >> 2;       // 2 warps along N (32 cols each)

    float acc[3][2][4][4];
#pragma unroll
    for (int g = 0; g < 3; g++)
#pragma unroll
        for (int mi = 0; mi < 2; mi++)
#pragma unroll
            for (int ni = 0; ni < 4; ni++)
#pragma unroll
                for (int j = 0; j < 4; j++) acc[g][mi][ni][j] = 0.f;

    // single base addresses; all other offsets are compile-time immediates
    const uint32_t a_base = (uint32_t)__cvta_generic_to_shared(
        As + (wm * 32 + (lane & 15)) * AROW + (((lane >> 4) & 1) << 3));
    const uint32_t b_base = (uint32_t)__cvta_generic_to_shared(
        Bs + (wn * 32 + (lane & 7)) * AROW + (((lane >> 3) & 1) << 3));

    // ---- mainloop over K = 8 x 16 ----
#pragma unroll
    for (int kk = 0; kk < 8; kk++) {
        const uint32_t koff = kk * 32;               // 16 halves
        uint32_t ah[2][4];
#pragma unroll
        for (int mi = 0; mi < 2; mi++)
            ldsm4(ah[mi], a_base + mi * (16 * AROW * 2) + koff);
#pragma unroll
        for (int g = 0; g < 3; g++) {
#pragma unroll
            for (int ni = 0; ni < 4; ni++) {
                uint32_t br[2];
                ldsm2(br, b_base + g * (64 * AROW * 2) + ni * (8 * AROW * 2) + koff);
#pragma unroll
                for (int mi = 0; mi < 2; mi++)
                    mma16816(acc[g][mi][ni], ah[mi], br);
            }
        }
    }

    // ---- epilogue: gates + scatter store ----
#pragma unroll
    for (int mi = 0; mi < 2; mi++) {
#pragma unroll
        for (int ni = 0; ni < 4; ni++) {
            const int colL = wn * 32 + ni * 8 + (lane & 3) * 2;
            const float br0 = biasS[colL],       br1 = biasS[colL + 1];
            const float bz0 = biasS[64 + colL],  bz1 = biasS[64 + colL + 1];
            const float bn0 = biasS[128 + colL], bn1 = biasS[128 + colL + 1];
            const float bh0 = biasS[192 + colL], bh1 = biasS[192 + colL + 1];
#pragma unroll
            for (int hseg = 0; hseg < 2; hseg++) {
                const int m = m0 + wm * 32 + mi * 16 + (lane >> 2) + hseg * 8;
                const float r0 = fsigmoid(acc[0][mi][ni][hseg * 2 + 0] + br0);
                const float r1 = fsigmoid(acc[0][mi][ni][hseg * 2 + 1] + br1);
                const float z0 = fsigmoid(acc[1][mi][ni][hseg * 2 + 0] + bz0);
                const float z1 = fsigmoid(acc[1][mi][ni][hseg * 2 + 1] + bz1);
                const float n0 = ftanh(acc[2][mi][ni][hseg * 2 + 0] + bn0 + r0 * bh0);
                const float n1 = ftanh(acc[2][mi][ni][hseg * 2 + 1] + bn1 + r1 * bh1);
                const float h0 = (1.f - z0) * n0;
                const float h1 = (1.f - z1) * n1;

                const int b = m >> 9;                // m / S
                const int s = m & 511;
                size_t o;
                if (s < SEQ - 1)
                    o = (size_t)(m - b) * HDIM + (hd0 + colL);      // H[b,s,:]
                else
                    o = H_TAIL + (size_t)b * HDIM + (hd0 + colL);   // h_last
                *(float2*)(out + o) = make_float2(h0, h1);
            }
        }
    }
}

// ---------------------------------------------------------------------------
extern "C" void kernel_launch(void* const* d_in, const int* in_sizes, int n_in,
                              void* d_out, int out_size) {
    const float* x     = (const float*)d_in[0];
    const float* w_emb = (const float*)d_in[1];
    const float* b_emb = (const float*)d_in[2];
    const float* w_ih  = (const float*)d_in[3];
    const float* b_ih  = (const float*)d_in[4];
    const float* b_hh  = (const float*)d_in[5];
    float* out = (float*)d_out;
    (void)in_sizes; (void)n_in; (void)out_size;

    cudaFuncSetAttribute(fused_main, cudaFuncAttributeMaxDynamicSharedMemorySize,
                         SMEM_BYTES);

    precomp_W_part<<<dim3(192, 4), 128>>>(w_ih, w_emb);
    precomp_W_reduce<<<192, 256>>>();
    precomp_bias<<<192, 256>>>(w_ih, b_emb, b_ih, b_hh);

    dim3 grid(HDIM / 64, MTOT / 128);   // (8, 512) — hd fastest
    fused_main<<<grid, 256, SMEM_BYTES>>>(x, b_hh, out);
}

// round 5
// speedup vs baseline: 2.1287x; 1.0411x over previous
#include <cuda_runtime.h>
#include <cuda_fp16.h>
#include <cstdint>
#include <math.h>

// Problem constants: B=128, S=512, I=128, Hd=512
#define IDIM    128
#define HDIM    512
#define G3      1536
#define MTOT    65536
#define SEQ     512
#define H_TAIL  33488896ull      // B*(S-1)*Hd

// Scratch (allocation-free rule: __device__ globals)
__device__ __half g_Wh[G3 * IDIM];          // fused fp16 weight W = w_ih @ w_emb
__device__ float  g_Wpart[4 * G3 * IDIM];   // K-split partials
__device__ float  g_bias[G3];               // fused bias
__device__ __half g_X16[MTOT * IDIM];       // x pre-converted to fp16 (16.8 MB)

// ===========================================================================
// Precompute: x -> fp16   (2048 blocks x 256 thr, 4 float4 each)
// ===========================================================================
__global__ void precomp_x16(const float* __restrict__ x) {
    const int v = blockIdx.x * 1024 + threadIdx.x;   // float4 index base
#pragma unroll
    for (int it = 0; it < 4; it++) {
        const int idx = v + it * 256;
        const float4 f = ((const float4*)x)[idx];
        __half2 p0 = __floats2half2_rn(f.x, f.y);
        __half2 p1 = __floats2half2_rn(f.z, f.w);
        ((uint2*)g_X16)[idx] = make_uint2(*(uint32_t*)&p0, *(uint32_t*)&p1);
    }
}

// ===========================================================================
// Precompute: W = w_ih @ w_emb  (K-split + deterministic reduce)
// ===========================================================================
__global__ void precomp_W_part(const float* __restrict__ w_ih,
                               const float* __restrict__ w_emb) {
    __shared__ float wihs[8][128];
    const int g0 = blockIdx.x * 8, chunk = blockIdx.y, h0 = chunk * 128;
    const int tid = threadIdx.x;
    {
        const float4* src = (const float4*)(w_ih + (size_t)g0 * 512 + h0);
        float4* dst = (float4*)&wihs[0][0];
#pragma unroll
        for (int it = 0; it < 2; it++) {
            const int idx = tid + it * 128;
            dst[(idx >> 5) * 32 + (idx & 31)] = src[(idx >> 5) * 128 + (idx & 31)];
        }
    }
    __syncthreads();
    const int i = tid;
    float acc[8] = {0.f,0.f,0.f,0.f,0.f,0.f,0.f,0.f};
#pragma unroll 4
    for (int h = 0; h < 128; h++) {
        const float we = w_emb[(h0 + h) * IDIM + i];
#pragma unroll
        for (int g = 0; g < 8; g++) acc[g] = fmaf(wihs[g][h], we, acc[g]);
    }
#pragma unroll
    for (int g = 0; g < 8; g++)
        g_Wpart[(size_t)chunk * (G3 * IDIM) + (size_t)(g0 + g) * IDIM + i] = acc[g];
}

__global__ void precomp_W_reduce() {
    const int v = blockIdx.x * 256 + threadIdx.x;
    const float4 a = ((const float4*)g_Wpart)[v];
    const float4 b = ((const float4*)g_Wpart)[v + 49152];
    const float4 c = ((const float4*)g_Wpart)[v + 2 * 49152];
    const float4 d = ((const float4*)g_Wpart)[v + 3 * 49152];
    __half2 h01 = __halves2half2(__float2half_rn(a.x + b.x + c.x + d.x),
                                 __float2half_rn(a.y + b.y + c.y + d.y));
    __half2 h23 = __halves2half2(__float2half_rn(a.z + b.z + c.z + d.z),
                                 __float2half_rn(a.w + b.w + c.w + d.w));
    ((__half2*)g_Wh)[v * 2]     = h01;
    ((__half2*)g_Wh)[v * 2 + 1] = h23;
}

__global__ void precomp_bias(const float* __restrict__ w_ih,
                             const float* __restrict__ b_emb,
                             const float* __restrict__ b_ih,
                             const float* __restrict__ b_hh) {
    const int warp = threadIdx.x >> 5, lane = threadIdx.x & 31;
    const int g = blockIdx.x * 8 + warp;
    const float* wg = w_ih + (size_t)g * 512;
    float acc = 0.f;
#pragma unroll
    for (int h = lane; h < 512; h += 32) acc = fmaf(wg[h], b_emb[h], acc);
#pragma unroll
    for (int off = 16; off; off >>= 1) acc += __shfl_xor_sync(0xffffffffu, acc, off);
    if (lane == 0) {
        float v = acc + b_ih[g];
        if (g < 1024) v += b_hh[g];
        g_bias[g] = v;
    }
}

// ===========================================================================
// asm helpers
// ===========================================================================
__device__ __forceinline__ void ldsm4(uint32_t* r, uint32_t addr) {
    asm volatile("ldmatrix.sync.aligned.m8n8.x4.shared.b16 {%0,%1,%2,%3}, [%4];\n"
                 : "=r"(r[0]), "=r"(r[1]), "=r"(r[2]), "=r"(r[3]) : "r"(addr));
}
__device__ __forceinline__ void mma16816(float* c, const uint32_t* a, const uint32_t* b) {
    asm volatile("mma.sync.aligned.m16n8k16.row.col.f32.f16.f16.f32 "
                 "{%0,%1,%2,%3}, {%4,%5,%6,%7}, {%8,%9}, {%0,%1,%2,%3};\n"
                 : "+f"(c[0]), "+f"(c[1]), "+f"(c[2]), "+f"(c[3])
                 : "r"(a[0]), "r"(a[1]), "r"(a[2]), "r"(a[3]), "r"(b[0]), "r"(b[1]));
}
__device__ __forceinline__ float fast_ex2(float x) {
    float y; asm("ex2.approx.f32 %0, %1;" : "=f"(y) : "f"(x)); return y;
}
__device__ __forceinline__ float fast_rcp(float x) {
    float y; asm("rcp.approx.f32 %0, %1;" : "=f"(y) : "f"(x)); return y;
}
__device__ __forceinline__ float fsigmoid(float x) {
    return fast_rcp(1.f + fast_ex2(-1.44269504f * x));
}
__device__ __forceinline__ float ftanh(float x) {
    return 1.f - 2.f * fast_rcp(1.f + fast_ex2(2.88539008f * x));
}

// ===========================================================================
// Fused main kernel:
//   gi = x_fp16 @ W_fp16^T + bias   (three 128x64 gate GEMMs per CTA)
//   h  = (1 - sig(gz)) * tanh(gn + sig(gr) * b_hn)
// grid = (8 hd, 512 m) — hd fastest so L2 shares the x tile.
// 256 threads: 8 warps = 4 (M) x 2 (N); 2 CTAs/SM.
// B fragments fetched with ldmatrix.x4 (n16 x k16 per load, gate-batched).
// ===========================================================================
#define AROW 136                 // padded row stride in halves (272 B)
#define SMEM_BYTES 88064

__global__ __launch_bounds__(256, 2)
void fused_main(const float* __restrict__ b_hh,
                float* __restrict__ out) {
    extern __shared__ __align__(16) char smem_raw[];
    __half* As = (__half*)smem_raw;                  // 128 x 136
    __half* Bs = As + 128 * AROW;                    // 3 gates x 64 x 136
    float*  biasS = (float*)(Bs + 3 * 64 * AROW);    // [4][64]

    const int tid = threadIdx.x;
    const int hd0 = blockIdx.x * 64;
    const int m0  = blockIdx.y * 128;

    // ---- A: copy pre-converted fp16 x tile (128 x 128 = 2048 int4) ----
    {
        const int4* xs = (const int4*)(g_X16 + (size_t)m0 * IDIM);
#pragma unroll
        for (int it = 0; it < 8; it++) {
            const int idx = tid + it * 256;          // 0..2047
            const int row = idx >> 4;
            const int c   = idx & 15;
            *(int4*)(As + row * AROW + c * 8) = xs[idx];
        }
    }
    // ---- B: 3 gate tiles (64 rows x 128 halves each) ----
    {
        const int4* ws = (const int4*)g_Wh;
#pragma unroll
        for (int it = 0; it < 12; it++) {
            const int idx  = tid + it * 256;         // 0..3071
            const int gate = idx >> 10;
            const int rem  = idx & 1023;
            const int r    = rem >> 4;
            const int c    = rem & 15;
            const int grow = gate * HDIM + hd0 + r;
            *(int4*)(Bs + gate * (64 * AROW) + r * AROW + c * 8) = ws[grow * 16 + c];
        }
    }
    if (tid < 64) {
        const int hd = hd0 + tid;
        biasS[tid]       = g_bias[hd];               // r
        biasS[64 + tid]  = g_bias[HDIM + hd];        // z
        biasS[128 + tid] = g_bias[2 * HDIM + hd];    // n (linear)
        biasS[192 + tid] = b_hh[2 * HDIM + hd];      // b_hn
    }
    __syncthreads();

    const int lane = tid & 31;
    const int warp = tid >> 5;
    const int wm = warp & 3;        // 4 warps along M (32 rows each)
    const int wn = warp >> 2;       // 2 warps along N (32 cols each)

    float acc[3][2][4][4];
#pragma unroll
    for (int g = 0; g < 3; g++)
#pragma unroll
        for (int mi = 0; mi < 2; mi++)
#pragma unroll
            for (int ni = 0; ni < 4; ni++)
#pragma unroll
                for (int j = 0; j < 4; j++) acc[g][mi][ni][j] = 0.f;

    // A x4 base: rows wm*32 + (lane&15), col half = (lane>>4)*8
    const uint32_t a_base = (uint32_t)__cvta_generic_to_shared(
        As + (wm * 32 + (lane & 15)) * AROW + (((lane >> 4) & 1) << 3));
    // B x4 base: matrices [n0-7,k0-7][n0-7,k8-15][n8-15,k0-7][n8-15,k8-15]
    //   lanes 0-7 -> m0, 8-15 -> m1, 16-23 -> m2, 24-31 -> m3
    const int brow = (lane & 7) + (((lane >> 4) & 1) << 3);
    const int bcol = ((lane >> 3) & 1) << 3;
    const uint32_t b_base = (uint32_t)__cvta_generic_to_shared(
        Bs + (wn * 32 + brow) * AROW + bcol);

    // ---- mainloop over K = 8 x 16 ----
#pragma unroll
    for (int kk = 0; kk < 8; kk++) {
        const uint32_t koff = kk * 32;               // 16 halves = 32 B
        uint32_t ah[2][4];
#pragma unroll
        for (int mi = 0; mi < 2; mi++)
            ldsm4(ah[mi], a_base + mi * (16 * AROW * 2) + koff);
#pragma unroll
        for (int g = 0; g < 3; g++) {
#pragma unroll
            for (int p = 0; p < 2; p++) {            // ni pairs {0,1},{2,3}
                uint32_t br[4];
                ldsm4(br, b_base + g * (64 * AROW * 2) + p * (16 * AROW * 2) + koff);
#pragma unroll
                for (int mi = 0; mi < 2; mi++) {
                    mma16816(acc[g][mi][2 * p],     ah[mi], br);      // b0,b1
                    mma16816(acc[g][mi][2 * p + 1], ah[mi], br + 2);  // b2,b3
                }
            }
        }
    }

    // ---- epilogue: gates + scatter store ----
#pragma unroll
    for (int mi = 0; mi < 2; mi++) {
#pragma unroll
        for (int ni = 0; ni < 4; ni++) {
            const int colL = wn * 32 + ni * 8 + (lane & 3) * 2;
            const float br0 = biasS[colL],       br1 = biasS[colL + 1];
            const float bz0 = biasS[64 + colL],  bz1 = biasS[64 + colL + 1];
            const float bn0 = biasS[128 + colL], bn1 = biasS[128 + colL + 1];
            const float bh0 = biasS[192 + colL], bh1 = biasS[192 + colL + 1];
#pragma unroll
            for (int hseg = 0; hseg < 2; hseg++) {
                const int m = m0 + wm * 32 + mi * 16 + (lane >> 2) + hseg * 8;
                const float r0 = fsigmoid(acc[0][mi][ni][hseg * 2 + 0] + br0);
                const float r1 = fsigmoid(acc[0][mi][ni][hseg * 2 + 1] + br1);
                const float z0 = fsigmoid(acc[1][mi][ni][hseg * 2 + 0] + bz0);
                const float z1 = fsigmoid(acc[1][mi][ni][hseg * 2 + 1] + bz1);
                const float n0 = ftanh(acc[2][mi][ni][hseg * 2 + 0] + bn0 + r0 * bh0);
                const float n1 = ftanh(acc[2][mi][ni][hseg * 2 + 1] + bn1 + r1 * bh1);
                const float h0 = (1.f - z0) * n0;
                const float h1 = (1.f - z1) * n1;

                const int b = m >> 9;                // m / S
                const int s = m & 511;
                size_t o;
                if (s < SEQ - 1)
                    o = (size_t)(m - b) * HDIM + (hd0 + colL);      // H[b,s,:]
                else
                    o = H_TAIL + (size_t)b * HDIM + (hd0 + colL);   // h_last
                *(float2*)(out + o) = make_float2(h0, h1);
            }
        }
    }
}

// ===========================================================================
extern "C" void kernel_launch(void* const* d_in, const int* in_sizes, int n_in,
                              void* d_out, int out_size) {
    const float* x     = (const float*)d_in[0];
    const float* w_emb = (const float*)d_in[1];
    const float* b_emb = (const float*)d_in[2];
    const float* w_ih  = (const float*)d_in[3];
    const float* b_ih  = (const float*)d_in[4];
    const float* b_hh  = (const float*)d_in[5];
    float* out = (float*)d_out;
    (void)in_sizes; (void)n_in; (void)out_size;

    cudaFuncSetAttribute(fused_main, cudaFuncAttributeMaxDynamicSharedMemorySize,
                         SMEM_BYTES);

    precomp_x16<<<2048, 256>>>(x);
    precomp_W_part<<<dim3(192, 4), 128>>>(w_ih, w_emb);
    precomp_W_reduce<<<192, 256>>>();
    precomp_bias<<<192, 256>>>(w_ih, b_emb, b_ih, b_hh);

    dim3 grid(HDIM / 64, MTOT / 128);   // (8, 512) — hd fastest
    fused_main<<<grid, 256, SMEM_BYTES>>>(b_hh, out);
}

// round 6
// speedup vs baseline: 2.7123x; 1.2742x over previous
#include <cuda_runtime.h>
#include <cuda_fp16.h>
#include <cstdint>
#include <math.h>

// Problem constants: B=128, S=512, I=128, Hd=512
#define IDIM    128
#define HDIM    512
#define G3      1536
#define MTOT    65536
#define SEQ     512
#define H_TAIL  33488896ull      // B*(S-1)*Hd

// Scratch (allocation-free rule: __device__ globals)
__device__ __half g_Wh[G3 * IDIM];          // fused fp16 weight W = w_ih @ w_emb
__device__ float  g_Wpart[4 * G3 * IDIM];   // K-split partials
__device__ float  g_bias[G3];               // fused bias
__device__ __half g_X16[MTOT * IDIM];       // x pre-converted to fp16 (16.8 MB)

// ===========================================================================
// Precompute: x -> fp16   (2048 blocks x 256 thr, 4 float4 each)
// ===========================================================================
__global__ void precomp_x16(const float* __restrict__ x) {
    const int v = blockIdx.x * 1024 + threadIdx.x;
#pragma unroll
    for (int it = 0; it < 4; it++) {
        const int idx = v + it * 256;
        const float4 f = ((const float4*)x)[idx];
        __half2 p0 = __floats2half2_rn(f.x, f.y);
        __half2 p1 = __floats2half2_rn(f.z, f.w);
        ((uint2*)g_X16)[idx] = make_uint2(*(uint32_t*)&p0, *(uint32_t*)&p1);
    }
}

// ===========================================================================
// Precompute: W = w_ih @ w_emb  (K-split + deterministic reduce)
// ===========================================================================
__global__ void precomp_W_part(const float* __restrict__ w_ih,
                               const float* __restrict__ w_emb) {
    __shared__ float wihs[8][128];
    const int g0 = blockIdx.x * 8, chunk = blockIdx.y, h0 = chunk * 128;
    const int tid = threadIdx.x;
    {
        const float4* src = (const float4*)(w_ih + (size_t)g0 * 512 + h0);
        float4* dst = (float4*)&wihs[0][0];
#pragma unroll
        for (int it = 0; it < 2; it++) {
            const int idx = tid + it * 128;
            dst[(idx >> 5) * 32 + (idx & 31)] = src[(idx >> 5) * 128 + (idx & 31)];
        }
    }
    __syncthreads();
    const int i = tid;
    float acc[8] = {0.f,0.f,0.f,0.f,0.f,0.f,0.f,0.f};
#pragma unroll 4
    for (int h = 0; h < 128; h++) {
        const float we = w_emb[(h0 + h) * IDIM + i];
#pragma unroll
        for (int g = 0; g < 8; g++) acc[g] = fmaf(wihs[g][h], we, acc[g]);
    }
#pragma unroll
    for (int g = 0; g < 8; g++)
        g_Wpart[(size_t)chunk * (G3 * IDIM) + (size_t)(g0 + g) * IDIM + i] = acc[g];
}

__global__ void precomp_W_reduce() {
    const int v = blockIdx.x * 256 + threadIdx.x;
    const float4 a = ((const float4*)g_Wpart)[v];
    const float4 b = ((const float4*)g_Wpart)[v + 49152];
    const float4 c = ((const float4*)g_Wpart)[v + 2 * 49152];
    const float4 d = ((const float4*)g_Wpart)[v + 3 * 49152];
    __half2 h01 = __halves2half2(__float2half_rn(a.x + b.x + c.x + d.x),
                                 __float2half_rn(a.y + b.y + c.y + d.y));
    __half2 h23 = __halves2half2(__float2half_rn(a.z + b.z + c.z + d.z),
                                 __float2half_rn(a.w + b.w + c.w + d.w));
    ((__half2*)g_Wh)[v * 2]     = h01;
    ((__half2*)g_Wh)[v * 2 + 1] = h23;
}

__global__ void precomp_bias(const float* __restrict__ w_ih,
                             const float* __restrict__ b_emb,
                             const float* __restrict__ b_ih,
                             const float* __restrict__ b_hh) {
    const int warp = threadIdx.x >> 5, lane = threadIdx.x & 31;
    const int g = blockIdx.x * 8 + warp;
    const float* wg = w_ih + (size_t)g * 512;
    float acc = 0.f;
#pragma unroll
    for (int h = lane; h < 512; h += 32) acc = fmaf(wg[h], b_emb[h], acc);
#pragma unroll
    for (int off = 16; off; off >>= 1) acc += __shfl_xor_sync(0xffffffffu, acc, off);
    if (lane == 0) {
        float v = acc + b_ih[g];
        if (g < 1024) v += b_hh[g];
        g_bias[g] = v;
    }
}

// ===========================================================================
// asm helpers
// ===========================================================================
__device__ __forceinline__ void ldsm4(uint32_t* r, uint32_t addr) {
    asm volatile("ldmatrix.sync.aligned.m8n8.x4.shared.b16 {%0,%1,%2,%3}, [%4];\n"
                 : "=r"(r[0]), "=r"(r[1]), "=r"(r[2]), "=r"(r[3]) : "r"(addr));
}
__device__ __forceinline__ void mma16816(float* c, const uint32_t* a, const uint32_t* b) {
    asm volatile("mma.sync.aligned.m16n8k16.row.col.f32.f16.f16.f32 "
                 "{%0,%1,%2,%3}, {%4,%5,%6,%7}, {%8,%9}, {%0,%1,%2,%3};\n"
                 : "+f"(c[0]), "+f"(c[1]), "+f"(c[2]), "+f"(c[3])
                 : "r"(a[0]), "r"(a[1]), "r"(a[2]), "r"(a[3]), "r"(b[0]), "r"(b[1]));
}
// Single-MUFU tanh (sm_75+). sigmoid(x) = 0.5*tanh(x/2) + 0.5  -> 1 MUFU + FMA.
__device__ __forceinline__ float tanh_ap(float x) {
    float y; asm("tanh.approx.f32 %0, %1;" : "=f"(y) : "f"(x)); return y;
}
__device__ __forceinline__ float fsigmoid(float x) {
    return fmaf(0.5f, tanh_ap(0.5f * x), 0.5f);
}

// ===========================================================================
// Fused main kernel:
//   gi = x_fp16 @ W_fp16^T + bias   (three 128x64 gate GEMMs per CTA)
//   h  = (1 - sig(gz)) * tanh(gn + sig(gr) * b_hn)
// grid = (8 hd, 512 m) — hd fastest so L2 shares the x tile.
// 256 threads: 8 warps = 4 (M) x 2 (N); 2 CTAs/SM.
// ===========================================================================
#define AROW 136                 // padded row stride in halves (272 B)
#define SMEM_BYTES 88064

__global__ __launch_bounds__(256, 2)
void fused_main(const float* __restrict__ b_hh,
                float* __restrict__ out) {
    extern __shared__ __align__(16) char smem_raw[];
    __half* As = (__half*)smem_raw;                  // 128 x 136
    __half* Bs = As + 128 * AROW;                    // 3 gates x 64 x 136
    float*  biasS = (float*)(Bs + 3 * 64 * AROW);    // [4][64]

    const int tid = threadIdx.x;
    const int hd0 = blockIdx.x * 64;
    const int m0  = blockIdx.y * 128;

    // ---- A: copy pre-converted fp16 x tile (128 x 128 = 2048 int4) ----
    {
        const int4* xs = (const int4*)(g_X16 + (size_t)m0 * IDIM);
#pragma unroll
        for (int it = 0; it < 8; it++) {
            const int idx = tid + it * 256;
            const int row = idx >> 4;
            const int c   = idx & 15;
            *(int4*)(As + row * AROW + c * 8) = xs[idx];
        }
    }
    // ---- B: 3 gate tiles (64 rows x 128 halves each) ----
    {
        const int4* ws = (const int4*)g_Wh;
#pragma unroll
        for (int it = 0; it < 12; it++) {
            const int idx  = tid + it * 256;
            const int gate = idx >> 10;
            const int rem  = idx & 1023;
            const int r    = rem >> 4;
            const int c    = rem & 15;
            const int grow = gate * HDIM + hd0 + r;
            *(int4*)(Bs + gate * (64 * AROW) + r * AROW + c * 8) = ws[grow * 16 + c];
        }
    }
    if (tid < 64) {
        const int hd = hd0 + tid;
        biasS[tid]       = g_bias[hd];               // r
        biasS[64 + tid]  = g_bias[HDIM + hd];        // z
        biasS[128 + tid] = g_bias[2 * HDIM + hd];    // n (linear)
        biasS[192 + tid] = b_hh[2 * HDIM + hd];      // b_hn
    }
    __syncthreads();

    const int lane = tid & 31;
    const int warp = tid >> 5;
    const int wm = warp & 3;        // 4 warps along M (32 rows each)
    const int wn = warp >> 2;       // 2 warps along N (32 cols each)

    float acc[3][2][4][4];
#pragma unroll
    for (int g = 0; g < 3; g++)
#pragma unroll
        for (int mi = 0; mi < 2; mi++)
#pragma unroll
            for (int ni = 0; ni < 4; ni++)
#pragma unroll
                for (int j = 0; j < 4; j++) acc[g][mi][ni][j] = 0.f;

    const uint32_t a_base = (uint32_t)__cvta_generic_to_shared(
        As + (wm * 32 + (lane & 15)) * AROW + (((lane >> 4) & 1) << 3));
    const int brow = (lane & 7) + (((lane >> 4) & 1) << 3);
    const int bcol = ((lane >> 3) & 1) << 3;
    const uint32_t b_base = (uint32_t)__cvta_generic_to_shared(
        Bs + (wn * 32 + brow) * AROW + bcol);

    // ---- mainloop over K = 8 x 16 ----
#pragma unroll
    for (int kk = 0; kk < 8; kk++) {
        const uint32_t koff = kk * 32;
        uint32_t ah[2][4];
#pragma unroll
        for (int mi = 0; mi < 2; mi++)
            ldsm4(ah[mi], a_base + mi * (16 * AROW * 2) + koff);
#pragma unroll
        for (int g = 0; g < 3; g++) {
#pragma unroll
            for (int p = 0; p < 2; p++) {
                uint32_t br[4];
                ldsm4(br, b_base + g * (64 * AROW * 2) + p * (16 * AROW * 2) + koff);
#pragma unroll
                for (int mi = 0; mi < 2; mi++) {
                    mma16816(acc[g][mi][2 * p],     ah[mi], br);
                    mma16816(acc[g][mi][2 * p + 1], ah[mi], br + 2);
                }
            }
        }
    }

    // ---- epilogue: gates (3 MUFU/element) + streaming scatter store ----
#pragma unroll
    for (int mi = 0; mi < 2; mi++) {
#pragma unroll
        for (int ni = 0; ni < 4; ni++) {
            const int colL = wn * 32 + ni * 8 + (lane & 3) * 2;
            const float br0 = biasS[colL],       br1 = biasS[colL + 1];
            const float bz0 = biasS[64 + colL],  bz1 = biasS[64 + colL + 1];
            const float bn0 = biasS[128 + colL], bn1 = biasS[128 + colL + 1];
            const float bh0 = biasS[192 + colL], bh1 = biasS[192 + colL + 1];
#pragma unroll
            for (int hseg = 0; hseg < 2; hseg++) {
                const int m = m0 + wm * 32 + mi * 16 + (lane >> 2) + hseg * 8;
                const float r0 = fsigmoid(acc[0][mi][ni][hseg * 2 + 0] + br0);
                const float r1 = fsigmoid(acc[0][mi][ni][hseg * 2 + 1] + br1);
                const float z0 = fsigmoid(acc[1][mi][ni][hseg * 2 + 0] + bz0);
                const float z1 = fsigmoid(acc[1][mi][ni][hseg * 2 + 1] + bz1);
                const float n0 = tanh_ap(acc[2][mi][ni][hseg * 2 + 0] + bn0 + r0 * bh0);
                const float n1 = tanh_ap(acc[2][mi][ni][hseg * 2 + 1] + bn1 + r1 * bh1);
                const float h0 = (1.f - z0) * n0;
                const float h1 = (1.f - z1) * n1;

                const int b = m >> 9;
                const int s = m & 511;
                size_t o;
                if (s < SEQ - 1)
                    o = (size_t)(m - b) * HDIM + (hd0 + colL);      // H[b,s,:]
                else
                    o = H_TAIL + (size_t)b * HDIM + (hd0 + colL);   // h_last
                __stcs((float2*)(out + o), make_float2(h0, h1));
            }
        }
    }
}

// ===========================================================================
extern "C" void kernel_launch(void* const* d_in, const int* in_sizes, int n_in,
                              void* d_out, int out_size) {
    const float* x     = (const float*)d_in[0];
    const float* w_emb = (const float*)d_in[1];
    const float* b_emb = (const float*)d_in[2];
    const float* w_ih  = (const float*)d_in[3];
    const float* b_ih  = (const float*)d_in[4];
    const float* b_hh  = (const float*)d_in[5];
    float* out = (float*)d_out;
    (void)in_sizes; (void)n_in; (void)out_size;

    cudaFuncSetAttribute(fused_main, cudaFuncAttributeMaxDynamicSharedMemorySize,
                         SMEM_BYTES);

    precomp_x16<<<2048, 256>>>(x);
    precomp_W_part<<<dim3(192, 4), 128>>>(w_ih, w_emb);
    precomp_W_reduce<<<192, 256>>>();
    precomp_bias<<<192, 256>>>(w_ih, b_emb, b_ih, b_hh);

    dim3 grid(HDIM / 64, MTOT / 128);   // (8, 512) — hd fastest
    fused_main<<<grid, 256, SMEM_BYTES>>>(b_hh, out);
}

// round 7
// speedup vs baseline: 2.9175x; 1.0757x over previous
#include <cuda_runtime.h>
#include <cuda_fp16.h>
#include <cstdint>
#include <math.h>

// Problem constants: B=128, S=512, I=128, Hd=512
#define IDIM    128
#define HDIM    512
#define G3      1536
#define MTOT    65536
#define SEQ     512
#define H_TAIL  33488896ull      // B*(S-1)*Hd

// Scratch (allocation-free rule: __device__ globals)
__device__ __half g_Wh[G3 * IDIM];          // fused fp16 weight W = w_ih @ w_emb
__device__ float  g_Wpart[4 * G3 * IDIM];   // K-split partials
__device__ float  g_bias[G3];               // fused bias
__device__ __half g_X16[MTOT * IDIM];       // x pre-converted to fp16 (16.8 MB)

// ===========================================================================
// Fat precompute kernel: blocks [0,2048) x->fp16, [2048,2816) W partials,
// [2816,3008) fused bias. All independent -> run concurrently in one launch.
// ===========================================================================
__global__ void precomp_all(const float* __restrict__ x,
                            const float* __restrict__ w_ih,
                            const float* __restrict__ w_emb,
                            const float* __restrict__ b_emb,
                            const float* __restrict__ b_ih,
                            const float* __restrict__ b_hh) {
    const int b = blockIdx.x, tid = threadIdx.x;
    if (b < 2048) {
        // ---- x -> fp16 ----
        const int v = b * 1024 + tid;
#pragma unroll
        for (int it = 0; it < 4; it++) {
            const int idx = v + it * 256;
            const float4 f = ((const float4*)x)[idx];
            __half2 p0 = __floats2half2_rn(f.x, f.y);
            __half2 p1 = __floats2half2_rn(f.z, f.w);
            ((uint2*)g_X16)[idx] = make_uint2(*(uint32_t*)&p0, *(uint32_t*)&p1);
        }
    } else if (b < 2816) {
        // ---- W partial: 8 g-rows x 128 i x 128 h-chunk ----
        __shared__ float wihs[8][128];
        const int q = b - 2048;                 // 0..767
        const int g0 = (q >> 2) * 8, h0 = (q & 3) * 128;
        {
            const float4* src = (const float4*)(w_ih + (size_t)g0 * 512 + h0);
            const int g = tid >> 5, c = tid & 31;      // 256 thr = 256 float4
            ((float4*)&wihs[0][0])[g * 32 + c] = src[g * 128 + c];
        }
        __syncthreads();
        const int i = tid & 127, gh = (tid >> 7) * 4;
        float acc[4] = {0.f, 0.f, 0.f, 0.f};
#pragma unroll 4
        for (int h = 0; h < 128; h++) {
            const float we = w_emb[(h0 + h) * IDIM + i];
#pragma unroll
            for (int g = 0; g < 4; g++) acc[g] = fmaf(wihs[gh + g][h], we, acc[g]);
        }
        const int chunk = q & 3;
#pragma unroll
        for (int g = 0; g < 4; g++)
            g_Wpart[(size_t)chunk * (G3 * IDIM) + (size_t)(g0 + gh + g) * IDIM + i] = acc[g];
    } else {
        // ---- bias[g] = w_ih[g]·b_emb + b_ih[g] + (g<1024 ? b_hh[g] : 0) ----
        const int q = b - 2816;                 // 0..191
        const int warp = tid >> 5, lane = tid & 31;
        const int g = q * 8 + warp;
        const float* wg = w_ih + (size_t)g * 512;
        float acc = 0.f;
#pragma unroll
        for (int h = lane; h < 512; h += 32) acc = fmaf(wg[h], b_emb[h], acc);
#pragma unroll
        for (int off = 16; off; off >>= 1) acc += __shfl_xor_sync(0xffffffffu, acc, off);
        if (lane == 0) {
            float v = acc + b_ih[g];
            if (g < 1024) v += b_hh[g];
            g_bias[g] = v;
        }
    }
}

__global__ void precomp_W_reduce() {
    const int v = blockIdx.x * 256 + threadIdx.x;
    const float4 a = ((const float4*)g_Wpart)[v];
    const float4 b = ((const float4*)g_Wpart)[v + 49152];
    const float4 c = ((const float4*)g_Wpart)[v + 2 * 49152];
    const float4 d = ((const float4*)g_Wpart)[v + 3 * 49152];
    __half2 h01 = __halves2half2(__float2half_rn(a.x + b.x + c.x + d.x),
                                 __float2half_rn(a.y + b.y + c.y + d.y));
    __half2 h23 = __halves2half2(__float2half_rn(a.z + b.z + c.z + d.z),
                                 __float2half_rn(a.w + b.w + c.w + d.w));
    ((__half2*)g_Wh)[v * 2]     = h01;
    ((__half2*)g_Wh)[v * 2 + 1] = h23;
}

// ===========================================================================
// asm helpers
// ===========================================================================
__device__ __forceinline__ uint32_t smem_u32(const void* p) {
    uint32_t a;
    asm("{ .reg .u64 t; cvta.to.shared.u64 t, %1; cvt.u32.u64 %0, t; }"
        : "=r"(a) : "l"(p));
    return a;
}
__device__ __forceinline__ void cp16(uint32_t dst, const void* src) {
    asm volatile("cp.async.cg.shared.global [%0], [%1], 16;"
                 :: "r"(dst), "l"(src) : "memory");
}
__device__ __forceinline__ void ldsm4(uint32_t* r, uint32_t addr) {
    asm volatile("ldmatrix.sync.aligned.m8n8.x4.shared.b16 {%0,%1,%2,%3}, [%4];\n"
                 : "=r"(r[0]), "=r"(r[1]), "=r"(r[2]), "=r"(r[3]) : "r"(addr));
}
__device__ __forceinline__ void mma16816(float* c, const uint32_t* a, const uint32_t* b) {
    asm volatile("mma.sync.aligned.m16n8k16.row.col.f32.f16.f16.f32 "
                 "{%0,%1,%2,%3}, {%4,%5,%6,%7}, {%8,%9}, {%0,%1,%2,%3};\n"
                 : "+f"(c[0]), "+f"(c[1]), "+f"(c[2]), "+f"(c[3])
                 : "r"(a[0]), "r"(a[1]), "r"(a[2]), "r"(a[3]), "r"(b[0]), "r"(b[1]));
}
__device__ __forceinline__ float tanh_ap(float x) {
    float y; asm("tanh.approx.f32 %0, %1;" : "=f"(y) : "f"(x)); return y;
}
__device__ __forceinline__ float fsigmoid(float x) {
    return fmaf(0.5f, tanh_ap(0.5f * x), 0.5f);
}

// ===========================================================================
// Persistent fused kernel.
// grid = (8 hd, 37 slots) = 296 CTAs (2/SM). Each CTA: pin B (3x64x128 fp16,
// swizzled, 48KB) once; loop m-tiles j = slot, slot+37, ... with cp.async
// double-buffered A (2 x 128x128 fp16 swizzled, 2x32KB).
// SMEM: [0,32768) A0, [32768,65536) A1, [65536,114688) B. Bias via __ldg (L1).
// Swizzle: 128B rows; 16B chunk index XOR (row&7).
// ===========================================================================
#define SMEM_BYTES 114688

__global__ __launch_bounds__(256, 2)
void fused_persist(const float* __restrict__ b_hh,
                   float* __restrict__ out) {
    extern __shared__ __align__(1024) char smem[];
    const uint32_t sb = smem_u32(smem);
    const uint32_t Bb = sb + 65536;

    const int tid  = threadIdx.x;
    const int hd0  = blockIdx.x * 64;
    const int slot = blockIdx.y;

    // ---- B tiles once (cp.async, group 0 together with first A tile) ----
    {
        const char* ws = (const char*)g_Wh;
#pragma unroll
        for (int it = 0; it < 12; it++) {
            const int idx  = tid + it * 256;         // 0..3071 16B chunks
            const int gate = idx >> 10;
            const int rem  = idx & 1023;
            const int r    = rem >> 4;
            const int ch   = rem & 15;
            const uint32_t dst = Bb + gate * 16384 + (ch >> 3) * 8192 + r * 128
                               + (((ch & 7) ^ (r & 7)) << 4);
            cp16(dst, ws + ((size_t)(gate * HDIM + hd0 + r) * IDIM + ch * 8) * 2);
        }
    }
    // ---- first A tile into buffer 0 ----
    {
        const char* xs = (const char*)(g_X16 + (size_t)(slot * 128) * IDIM);
#pragma unroll
        for (int it = 0; it < 8; it++) {
            const int idx = tid + it * 256;          // 0..2047 chunks
            const int row = idx >> 4, ch = idx & 15;
            const uint32_t dst = sb + (ch >> 3) * 16384 + row * 128
                               + (((ch & 7) ^ (row & 7)) << 4);
            cp16(dst, xs + idx * 16);
        }
    }
    asm volatile("cp.async.commit_group;" ::: "memory");

    // ---- per-lane constants ----
    const int lane = tid & 31, warp = tid >> 5;
    const int wm = warp & 3, wn = warp >> 2;
    const int ar = wm * 32 + (lane & 15);
    const uint32_t a_row = (uint32_t)ar * 128u;
    const uint32_t a7    = (uint32_t)(ar & 7) << 4;
    const uint32_t ahi   = (uint32_t)((lane >> 4) & 1) << 4;
    const int br = wn * 32 + (lane & 7) + (((lane >> 4) & 1) << 3);
    const uint32_t b_row = (uint32_t)br * 128u;
    const uint32_t b7    = (uint32_t)(br & 7) << 4;
    const uint32_t bhi   = (uint32_t)((lane >> 3) & 1) << 4;

    int cur = 0;
    for (int j = slot; j < 512; j += 37) {
        const int jn = j + 37;
        if (jn < 512) {
            const uint32_t ab = sb + (cur ^ 1) * 32768;
            const char* xs = (const char*)(g_X16 + (size_t)(jn * 128) * IDIM);
#pragma unroll
            for (int it = 0; it < 8; it++) {
                const int idx = tid + it * 256;
                const int row = idx >> 4, ch = idx & 15;
                const uint32_t dst = ab + (ch >> 3) * 16384 + row * 128
                                   + (((ch & 7) ^ (row & 7)) << 4);
                cp16(dst, xs + idx * 16);
            }
            asm volatile("cp.async.commit_group;" ::: "memory");
            asm volatile("cp.async.wait_group 1;" ::: "memory");
        } else {
            asm volatile("cp.async.wait_group 0;" ::: "memory");
        }
        __syncthreads();

        // ---- mainloop: three 128x64 gate GEMMs from buffers ----
        const uint32_t Ab = sb + cur * 32768;
        float acc[3][2][4][4];
#pragma unroll
        for (int g = 0; g < 3; g++)
#pragma unroll
            for (int mi = 0; mi < 2; mi++)
#pragma unroll
                for (int ni = 0; ni < 4; ni++)
#pragma unroll
                    for (int t = 0; t < 4; t++) acc[g][mi][ni][t] = 0.f;

#pragma unroll
        for (int kk = 0; kk < 8; kk++) {
            const uint32_t aoff = (uint32_t)(kk >> 2) * 16384u + a_row
                                + ((((uint32_t)(kk & 3) << 5) | ahi) ^ a7);
            uint32_t ah[2][4];
            ldsm4(ah[0], Ab + aoff);
            ldsm4(ah[1], Ab + aoff + 2048);          // mi=1: +16 rows
            const uint32_t boff = (uint32_t)(kk >> 2) * 8192u + b_row
                                + ((((uint32_t)(kk & 3) << 5) | bhi) ^ b7);
#pragma unroll
            for (int g = 0; g < 3; g++) {
#pragma unroll
                for (int p = 0; p < 2; p++) {
                    uint32_t bf[4];
                    ldsm4(bf, Bb + g * 16384 + boff + p * 2048);
#pragma unroll
                    for (int mi = 0; mi < 2; mi++) {
                        mma16816(acc[g][mi][2 * p],     ah[mi], bf);
                        mma16816(acc[g][mi][2 * p + 1], ah[mi], bf + 2);
                    }
                }
            }
        }
        __syncthreads();      // all warps done reading A buffer `cur`

        // ---- epilogue (overlaps next tile's cp.async fill) ----
        const int m0 = j * 128;
#pragma unroll
        for (int ni = 0; ni < 4; ni++) {
            const int colL = wn * 32 + ni * 8 + (lane & 3) * 2;
            const int hd = hd0 + colL;
            const float br0 = __ldg(&g_bias[hd]);
            const float br1 = __ldg(&g_bias[hd + 1]);
            const float bz0 = __ldg(&g_bias[HDIM + hd]);
            const float bz1 = __ldg(&g_bias[HDIM + hd + 1]);
            const float bn0 = __ldg(&g_bias[2 * HDIM + hd]);
            const float bn1 = __ldg(&g_bias[2 * HDIM + hd + 1]);
            const float bh0 = __ldg(&b_hh[2 * HDIM + hd]);
            const float bh1 = __ldg(&b_hh[2 * HDIM + hd + 1]);
#pragma unroll
            for (int mi = 0; mi < 2; mi++) {
#pragma unroll
                for (int hseg = 0; hseg < 2; hseg++) {
                    const int m = m0 + wm * 32 + mi * 16 + (lane >> 2) + hseg * 8;
                    const float r0 = fsigmoid(acc[0][mi][ni][hseg * 2 + 0] + br0);
                    const float r1 = fsigmoid(acc[0][mi][ni][hseg * 2 + 1] + br1);
                    const float z0 = fsigmoid(acc[1][mi][ni][hseg * 2 + 0] + bz0);
                    const float z1 = fsigmoid(acc[1][mi][ni][hseg * 2 + 1] + bz1);
                    const float n0 = tanh_ap(acc[2][mi][ni][hseg * 2 + 0] + bn0 + r0 * bh0);
                    const float n1 = tanh_ap(acc[2][mi][ni][hseg * 2 + 1] + bn1 + r1 * bh1);
                    const float h0 = (1.f - z0) * n0;
                    const float h1 = (1.f - z1) * n1;

                    const int bb = m >> 9;           // m / S
                    const int s  = m & 511;
                    size_t o;
                    if (s < SEQ - 1)
                        o = (size_t)(m - bb) * HDIM + hd;           // H[b,s,:]
                    else
                        o = H_TAIL + (size_t)bb * HDIM + hd;        // h_last
                    __stcs((float2*)(out + o), make_float2(h0, h1));
                }
            }
        }
        cur ^= 1;
    }
}

// ===========================================================================
extern "C" void kernel_launch(void* const* d_in, const int* in_sizes, int n_in,
                              void* d_out, int out_size) {
    const float* x     = (const float*)d_in[0];
    const float* w_emb = (const float*)d_in[1];
    const float* b_emb = (const float*)d_in[2];
    const float* w_ih  = (const float*)d_in[3];
    const float* b_ih  = (const float*)d_in[4];
    const float* b_hh  = (const float*)d_in[5];
    float* out = (float*)d_out;
    (void)in_sizes; (void)n_in; (void)out_size;

    cudaFuncSetAttribute(fused_persist, cudaFuncAttributeMaxDynamicSharedMemorySize,
                         SMEM_BYTES);

    precomp_all<<<3008, 256>>>(x, w_ih, w_emb, b_emb, b_ih, b_hh);
    precomp_W_reduce<<<192, 256>>>();

    dim3 grid(HDIM / 64, 37);            // 296 persistent CTAs (2/SM)
    fused_persist<<<grid, 256, SMEM_BYTES>>>(b_hh, out);
}

// round 9
// speedup vs baseline: 3.0935x; 1.0603x over previous
#include <cuda_runtime.h>
#include <cuda_fp16.h>
#include <cstdint>
#include <math.h>

// Problem constants: B=128, S=512, I=128, Hd=512
#define IDIM    128
#define HDIM    512
#define G3      1536
#define MTOT    65536
#define SEQ     512
#define H_TAIL  33488896ull      // B*(S-1)*Hd

// Scratch (allocation-free rule: __device__ globals)
__device__ __half g_Wh[G3 * IDIM];          // fused fp16 weight W = w_ih @ w_emb
__device__ float  g_Wpart[4 * G3 * IDIM];   // K-split partials
__device__ float  g_bias[G3];               // fused bias
__device__ __half g_X16[MTOT * IDIM];       // x pre-converted to fp16 (16.8 MB)

// ===========================================================================
// Fat precompute kernel: blocks [0,2048) x->fp16, [2048,2816) W partials,
// [2816,3008) fused bias. All independent -> concurrent in one launch.
// ===========================================================================
__global__ void precomp_all(const float* __restrict__ x,
                            const float* __restrict__ w_ih,
                            const float* __restrict__ w_emb,
                            const float* __restrict__ b_emb,
                            const float* __restrict__ b_ih,
                            const float* __restrict__ b_hh) {
    const int b = blockIdx.x, tid = threadIdx.x;
    if (b < 2048) {
        // ---- x -> fp16: 2 float4 loads -> 1 int4 store per iter ----
        // total int4 elems = MTOT*IDIM/8 = 1,048,576 = 2048 blk * 256 thr * 2 it
        const int v = b * 512 + tid;
#pragma unroll
        for (int it = 0; it < 2; it++) {
            const int idx = v + it * 256;           // 0..1048575
            const float4 f0 = ((const float4*)x)[2 * idx];
            const float4 f1 = ((const float4*)x)[2 * idx + 1];
            __half2 p0 = __floats2half2_rn(f0.x, f0.y);
            __half2 p1 = __floats2half2_rn(f0.z, f0.w);
            __half2 p2 = __floats2half2_rn(f1.x, f1.y);
            __half2 p3 = __floats2half2_rn(f1.z, f1.w);
            int4 o;
            o.x = *(int*)&p0; o.y = *(int*)&p1; o.z = *(int*)&p2; o.w = *(int*)&p3;
            ((int4*)g_X16)[idx] = o;
        }
    } else if (b < 2816) {
        // ---- W partial: 8 g-rows x 128 i x 128 h-chunk ----
        __shared__ float wihs[8][128];
        const int q = b - 2048;                 // 0..767
        const int g0 = (q >> 2) * 8, h0 = (q & 3) * 128;
        {
            const float4* src = (const float4*)(w_ih + (size_t)g0 * 512 + h0);
            const int g = tid >> 5, c = tid & 31;
            ((float4*)&wihs[0][0])[g * 32 + c] = src[g * 128 + c];
        }
        __syncthreads();
        const int i = tid & 127, gh = (tid >> 7) * 4;
        float acc[4] = {0.f, 0.f, 0.f, 0.f};
#pragma unroll 4
        for (int h = 0; h < 128; h++) {
            const float we = w_emb[(h0 + h) * IDIM + i];
#pragma unroll
            for (int g = 0; g < 4; g++) acc[g] = fmaf(wihs[gh + g][h], we, acc[g]);
        }
        const int chunk = q & 3;
#pragma unroll
        for (int g = 0; g < 4; g++)
            g_Wpart[(size_t)chunk * (G3 * IDIM) + (size_t)(g0 + gh + g) * IDIM + i] = acc[g];
    } else {
        // ---- bias[g] = w_ih[g]·b_emb + b_ih[g] + (g<1024 ? b_hh[g] : 0) ----
        const int q = b - 2816;
        const int warp = tid >> 5, lane = tid & 31;
        const int g = q * 8 + warp;
        const float* wg = w_ih + (size_t)g * 512;
        float acc = 0.f;
#pragma unroll
        for (int h = lane; h < 512; h += 32) acc = fmaf(wg[h], b_emb[h], acc);
#pragma unroll
        for (int off = 16; off; off >>= 1) acc += __shfl_xor_sync(0xffffffffu, acc, off);
        if (lane == 0) {
            float v = acc + b_ih[g];
            if (g < 1024) v += b_hh[g];
            g_bias[g] = v;
        }
    }
}

__global__ void precomp_W_reduce() {
    const int v = blockIdx.x * 256 + threadIdx.x;
    const float4 a = ((const float4*)g_Wpart)[v];
    const float4 b = ((const float4*)g_Wpart)[v + 49152];
    const float4 c = ((const float4*)g_Wpart)[v + 2 * 49152];
    const float4 d = ((const float4*)g_Wpart)[v + 3 * 49152];
    __half2 h01 = __halves2half2(__float2half_rn(a.x + b.x + c.x + d.x),
                                 __float2half_rn(a.y + b.y + c.y + d.y));
    __half2 h23 = __halves2half2(__float2half_rn(a.z + b.z + c.z + d.z),
                                 __float2half_rn(a.w + b.w + c.w + d.w));
    ((__half2*)g_Wh)[v * 2]     = h01;
    ((__half2*)g_Wh)[v * 2 + 1] = h23;
}

// ===========================================================================
// asm helpers
// ===========================================================================
__device__ __forceinline__ uint32_t smem_u32(const void* p) {
    uint32_t a;
    asm("{ .reg .u64 t; cvta.to.shared.u64 t, %1; cvt.u32.u64 %0, t; }"
        : "=r"(a) : "l"(p));
    return a;
}
__device__ __forceinline__ void cp16(uint32_t dst, const void* src) {
    asm volatile("cp.async.cg.shared.global [%0], [%1], 16;"
                 :: "r"(dst), "l"(src) : "memory");
}
__device__ __forceinline__ void ldsm4(uint32_t* r, uint32_t addr) {
    asm volatile("ldmatrix.sync.aligned.m8n8.x4.shared.b16 {%0,%1,%2,%3}, [%4];\n"
                 : "=r"(r[0]), "=r"(r[1]), "=r"(r[2]), "=r"(r[3]) : "r"(addr));
}
__device__ __forceinline__ void mma16816(float* c, const uint32_t* a, const uint32_t* b) {
    asm volatile("mma.sync.aligned.m16n8k16.row.col.f32.f16.f16.f32 "
                 "{%0,%1,%2,%3}, {%4,%5,%6,%7}, {%8,%9}, {%0,%1,%2,%3};\n"
                 : "+f"(c[0]), "+f"(c[1]), "+f"(c[2]), "+f"(c[3])
                 : "r"(a[0]), "r"(a[1]), "r"(a[2]), "r"(a[3]), "r"(b[0]), "r"(b[1]));
}
__device__ __forceinline__ float tanh_ap(float x) {
    float y; asm("tanh.approx.f32 %0, %1;" : "=f"(y) : "f"(x)); return y;
}
__device__ __forceinline__ float fsigmoid(float x) {
    return fmaf(0.5f, tanh_ap(0.5f * x), 0.5f);
}

// ===========================================================================
// Persistent fused kernel, 3-stage rotation on 2 A-buffers:
//   wait fill(j) -> mainloop(j) -> issue fill(j+74) -> epilogue(j)
// grid = (8 hd, 37 slots) = 296 CTAs (2/SM). B pinned once (48KB).
// SMEM: [0,32768) A0, [32768,65536) A1, [65536,114688) B.
// Swizzle: 128B rows; 16B chunk index XOR (row&7).
// ===========================================================================
#define SMEM_BYTES 114688

__global__ __launch_bounds__(256, 2)
void fused_persist(const float* __restrict__ b_hh,
                   float* __restrict__ out) {
    extern __shared__ __align__(1024) char smem[];
    const uint32_t sb = smem_u32(smem);
    const uint32_t Bb = sb + 65536;

    const int tid  = threadIdx.x;
    const int hd0  = blockIdx.x * 64;
    const int slot = blockIdx.y;

    // ---- group 0: B tiles + first A tile ----
    {
        const char* ws = (const char*)g_Wh;
#pragma unroll
        for (int it = 0; it < 12; it++) {
            const int idx  = tid + it * 256;
            const int gate = idx >> 10;
            const int rem  = idx & 1023;
            const int r    = rem >> 4;
            const int ch   = rem & 15;
            const uint32_t dst = Bb + gate * 16384 + (ch >> 3) * 8192 + r * 128
                               + (((ch & 7) ^ (r & 7)) << 4);
            cp16(dst, ws + ((size_t)(gate * HDIM + hd0 + r) * IDIM + ch * 8) * 2);
        }
        const char* xs = (const char*)(g_X16 + (size_t)(slot * 128) * IDIM);
#pragma unroll
        for (int it = 0; it < 8; it++) {
            const int idx = tid + it * 256;
            const int row = idx >> 4, ch = idx & 15;
            const uint32_t dst = sb + (ch >> 3) * 16384 + row * 128
                               + (((ch & 7) ^ (row & 7)) << 4);
            cp16(dst, xs + idx * 16);
        }
        asm volatile("cp.async.commit_group;" ::: "memory");
    }
    // ---- group 1: second A tile (j = slot+37, always < 512) ----
    {
        const char* xs = (const char*)(g_X16 + (size_t)((slot + 37) * 128) * IDIM);
#pragma unroll
        for (int it = 0; it < 8; it++) {
            const int idx = tid + it * 256;
            const int row = idx >> 4, ch = idx & 15;
            const uint32_t dst = sb + 32768 + (ch >> 3) * 16384 + row * 128
                               + (((ch & 7) ^ (row & 7)) << 4);
            cp16(dst, xs + idx * 16);
        }
        asm volatile("cp.async.commit_group;" ::: "memory");
    }

    // ---- per-lane constants ----
    const int lane = tid & 31, warp = tid >> 5;
    const int wm = warp & 3, wn = warp >> 2;
    const int ar = wm * 32 + (lane & 15);
    const uint32_t a_row = (uint32_t)ar * 128u;
    const uint32_t a7    = (uint32_t)(ar & 7) << 4;
    const uint32_t ahi   = (uint32_t)((lane >> 4) & 1) << 4;
    const int br = wn * 32 + (lane & 7) + (((lane >> 4) & 1) << 3);
    const uint32_t b_row = (uint32_t)br * 128u;
    const uint32_t b7    = (uint32_t)(br & 7) << 4;
    const uint32_t bhi   = (uint32_t)((lane >> 3) & 1) << 4;

    int cur = 0;
    for (int j = slot; j < 512; j += 37) {
        // wait for fill(j): keep <=1 newer group in flight, else drain fully
        if (j + 37 < 512) {
            asm volatile("cp.async.wait_group 1;" ::: "memory");
        } else {
            asm volatile("cp.async.wait_group 0;" ::: "memory");
        }
        __syncthreads();

        // ---- mainloop: three 128x64 gate GEMMs from buffer cur ----
        const uint32_t Ab = sb + cur * 32768;
        float acc[3][2][4][4];
#pragma unroll
        for (int g = 0; g < 3; g++)
#pragma unroll
            for (int mi = 0; mi < 2; mi++)
#pragma unroll
                for (int ni = 0; ni < 4; ni++)
#pragma unroll
                    for (int t = 0; t < 4; t++) acc[g][mi][ni][t] = 0.f;

#pragma unroll
        for (int kk = 0; kk < 8; kk++) {
            const uint32_t aoff = (uint32_t)(kk >> 2) * 16384u + a_row
                                + ((((uint32_t)(kk & 3) << 5) | ahi) ^ a7);
            uint32_t ah[2][4];
            ldsm4(ah[0], Ab + aoff);
            ldsm4(ah[1], Ab + aoff + 2048);          // mi=1: +16 rows
            const uint32_t boff = (uint32_t)(kk >> 2) * 8192u + b_row
                                + ((((uint32_t)(kk & 3) << 5) | bhi) ^ b7);
#pragma unroll
            for (int g = 0; g < 3; g++) {
#pragma unroll
                for (int p = 0; p < 2; p++) {
                    uint32_t bf[4];
                    ldsm4(bf, Bb + g * 16384 + boff + p * 2048);
#pragma unroll
                    for (int mi = 0; mi < 2; mi++) {
                        mma16816(acc[g][mi][2 * p],     ah[mi], bf);
                        mma16816(acc[g][mi][2 * p + 1], ah[mi], bf + 2);
                    }
                }
            }
        }
        __syncthreads();      // all warps done reading buffer `cur`

        // ---- issue fill(j+74) into buffer `cur` BEFORE epilogue ----
        if (j + 74 < 512) {
            const char* xs = (const char*)(g_X16 + (size_t)((j + 74) * 128) * IDIM);
#pragma unroll
            for (int it = 0; it < 8; it++) {
                const int idx = tid + it * 256;
                const int row = idx >> 4, ch = idx & 15;
                const uint32_t dst = Ab + (ch >> 3) * 16384 + row * 128
                                   + (((ch & 7) ^ (row & 7)) << 4);
                cp16(dst, xs + idx * 16);
            }
            asm volatile("cp.async.commit_group;" ::: "memory");
        }

        // ---- epilogue (overlaps the in-flight fill) ----
        const int m0 = j * 128;
#pragma unroll
        for (int ni = 0; ni < 4; ni++) {
            const int colL = wn * 32 + ni * 8 + (lane & 3) * 2;
            const int hd = hd0 + colL;
            const float br0 = __ldg(&g_bias[hd]);
            const float br1 = __ldg(&g_bias[hd + 1]);
            const float bz0 = __ldg(&g_bias[HDIM + hd]);
            const float bz1 = __ldg(&g_bias[HDIM + hd + 1]);
            const float bn0 = __ldg(&g_bias[2 * HDIM + hd]);
            const float bn1 = __ldg(&g_bias[2 * HDIM + hd + 1]);
            const float bh0 = __ldg(&b_hh[2 * HDIM + hd]);
            const float bh1 = __ldg(&b_hh[2 * HDIM + hd + 1]);
#pragma unroll
            for (int mi = 0; mi < 2; mi++) {
#pragma unroll
                for (int hseg = 0; hseg < 2; hseg++) {
                    const int m = m0 + wm * 32 + mi * 16 + (lane >> 2) + hseg * 8;
                    const float r0 = fsigmoid(acc[0][mi][ni][hseg * 2 + 0] + br0);
                    const float r1 = fsigmoid(acc[0][mi][ni][hseg * 2 + 1] + br1);
                    const float z0 = fsigmoid(acc[1][mi][ni][hseg * 2 + 0] + bz0);
                    const float z1 = fsigmoid(acc[1][mi][ni][hseg * 2 + 1] + bz1);
                    const float n0 = tanh_ap(acc[2][mi][ni][hseg * 2 + 0] + bn0 + r0 * bh0);
                    const float n1 = tanh_ap(acc[2][mi][ni][hseg * 2 + 1] + bn1 + r1 * bh1);
                    const float h0 = (1.f - z0) * n0;
                    const float h1 = (1.f - z1) * n1;

                    const int bb = m >> 9;
                    const int s  = m & 511;
                    size_t o;
                    if (s < SEQ - 1)
                        o = (size_t)(m - bb) * HDIM + hd;           // H[b,s,:]
                    else
                        o = H_TAIL + (size_t)bb * HDIM + hd;        // h_last
                    __stcs((float2*)(out + o), make_float2(h0, h1));
                }
            }
        }
        cur ^= 1;
    }
}

// ===========================================================================
extern "C" void kernel_launch(void* const* d_in, const int* in_sizes, int n_in,
                              void* d_out, int out_size) {
    const float* x     = (const float*)d_in[0];
    const float* w_emb = (const float*)d_in[1];
    const float* b_emb = (const float*)d_in[2];
    const float* w_ih  = (const float*)d_in[3];
    const float* b_ih  = (const float*)d_in[4];
    const float* b_hh  = (const float*)d_in[5];
    float* out = (float*)d_out;
    (void)in_sizes; (void)n_in; (void)out_size;

    cudaFuncSetAttribute(fused_persist, cudaFuncAttributeMaxDynamicSharedMemorySize,
                         SMEM_BYTES);

    precomp_all<<<3008, 256>>>(x, w_ih, w_emb, b_emb, b_ih, b_hh);
    precomp_W_reduce<<<192, 256>>>();

    dim3 grid(HDIM / 64, 37);            // 296 persistent CTAs (2/SM)
    fused_persist<<<grid, 256, SMEM_BYTES>>>(b_hh, out);
}